// round 6
// baseline (speedup 1.0000x reference)
#include <cuda_runtime.h>
#include <math.h>

#define T_TOK   65536
#define D_EMB   256
#define H_DIM   64
#define N_EXP   10
#define CHUNK   128          // tokens per FFN block (2 passes of 64)
#define XS_STR  68
#define HS_STR  68
#define NBLK_C  16384

typedef unsigned long long u64;

__device__ __forceinline__ u64 pack2(float lo, float hi) {
    u64 r; asm("mov.b64 %0,{%1,%2};" : "=l"(r) : "f"(lo), "f"(hi)); return r;
}
__device__ __forceinline__ void ffma2(u64& d, u64 a, u64 b) {
    asm("fma.rn.f32x2 %0,%1,%2,%0;" : "+l"(d) : "l"(a), "l"(b));
}
__device__ __forceinline__ u64 add2(u64 a, u64 b) {
    u64 r; asm("add.rn.f32x2 %0,%1,%2;" : "=l"(r) : "l"(a), "l"(b)); return r;
}
__device__ __forceinline__ u64 mul2(u64 a, u64 b) {
    u64 r; asm("mul.rn.f32x2 %0,%1,%2;" : "=l"(r) : "l"(a), "l"(b)); return r;
}
__device__ __forceinline__ float2 unpack2(u64 v) {
    float2 r; asm("mov.b64 {%0,%1},%2;" : "=f"(r.x), "=f"(r.y) : "l"(v)); return r;
}

// ---------------- scratch (zero-initialized at module load) -------------------
__device__ int   g_count[N_EXP];          // zeroed by k_final tail each call
__device__ int   g_bucket[N_EXP * T_TOK];
__device__ int   g_eidx [T_TOK * 2];
__device__ float g_gates[T_TOK * 2];
__device__ float g_part [(size_t)T_TOK * 2 * D_EMB];
__device__ float g_kd_part[NBLK_C];

// ---------------- kernel A: gating ---------------------------------------------
__global__ void __launch_bounds__(256) k_gate(const float* __restrict__ x,
                                              const float* __restrict__ wg) {
    __shared__ float wgs[N_EXP * D_EMB];          // transposed: [e][d], conflict-free
    int tid = threadIdx.x;
    for (int i = tid; i < D_EMB * N_EXP; i += 256) {
        int e = i / D_EMB, d = i - e * D_EMB;
        wgs[i] = wg[d * N_EXP + e];
    }
    __syncthreads();

    int warp = tid >> 5, lane = tid & 31;
    int t0 = blockIdx.x * 32 + warp * 4;
    for (int r = 0; r < 4; ++r) {
        int t = t0 + r;
        float part[N_EXP];
#pragma unroll
        for (int e = 0; e < N_EXP; ++e) part[e] = 0.f;
#pragma unroll
        for (int dd = 0; dd < 8; ++dd) {
            int d = dd * 32 + lane;
            float xv = x[(size_t)t * D_EMB + d];
#pragma unroll
            for (int e = 0; e < N_EXP; ++e)
                part[e] = fmaf(xv, wgs[e * D_EMB + d], part[e]);
        }
#pragma unroll
        for (int e = 0; e < N_EXP; ++e) {
#pragma unroll
            for (int off = 16; off; off >>= 1)
                part[e] += __shfl_xor_sync(0xffffffffu, part[e], off);
        }
        if (lane == 0) {
            float m0 = -1e30f; int e0 = 0;
#pragma unroll
            for (int e = 0; e < N_EXP; ++e) if (part[e] > m0) { m0 = part[e]; e0 = e; }
            float m1 = -1e30f; int e1 = 0;
#pragma unroll
            for (int e = 0; e < N_EXP; ++e) if (e != e0 && part[e] > m1) { m1 = part[e]; e1 = e; }
            float ex = expf(m1 - m0);
            float s  = 1.f + ex;
            float g0 = 1.f / s;
            float g1 = ex / s;
            g_eidx [2 * t]     = e0;  g_gates[2 * t]     = g0;
            g_eidx [2 * t + 1] = e1;  g_gates[2 * t + 1] = g1;
            int p0 = atomicAdd(&g_count[e0], 1);
            g_bucket[e0 * T_TOK + p0] = (t << 1);
            int p1 = atomicAdd(&g_count[e1], 1);
            g_bucket[e1 * T_TOK + p1] = (t << 1) | 1;
        }
    }
}

// ---------------- kernel B: expert-grouped FFN --------------------------------
// Weights read via broadcast LDG (L2-hot); SMEM holds only x/h tiles ->
// ~88 KB -> 2 blocks/SM (4 warps/SMSP) for latency hiding.
__global__ void __launch_bounds__(256, 2) k_ffn(const float* __restrict__ x,
                                                const float* __restrict__ w1,
                                                const float* __restrict__ b1,
                                                const float* __restrict__ w2,
                                                const float* __restrict__ b2) {
    int e = blockIdx.y;
    int n_total = g_count[e];
    int base = blockIdx.x * CHUNK;
    if (base >= n_total) return;

    extern __shared__ float sm[];
    float* xs  = sm;                              // [256][XS_STR] transposed x
    float* hs  = xs + D_EMB * XS_STR;             // [64][HS_STR]  transposed h
    float* gsh = hs + H_DIM * HS_STR;             // [64]
    int*   ash = (int*)(gsh + 64);                // [64]

    int tid = threadIdx.x;
    int tg = tid & 31;    // token pair idx: tokens tg*2, tg*2+1
    int hg = tid >> 5;    // warp id 0..7 -> h/o group of 8

    const float* w1e = w1 + (size_t)e * D_EMB * H_DIM + hg * 8;  // + d*64
    const float* w2e = w2 + (size_t)e * H_DIM * D_EMB;           // + k*256 + o

    float2 b1p[4];
#pragma unroll
    for (int j = 0; j < 4; ++j)
        b1p[j] = *(const float2*)(b1 + e * H_DIM + hg * 8 + j * 2);

    int s_stage  = tid & 63;
    int dq_stage = tid >> 6;

    for (int p = 0; p < CHUNK / 64; ++p) {
        int tbase = base + p * 64;
        if (tbase >= n_total) break;
        int nt = min(64, n_total - tbase);

        __syncthreads();
        if (tid < 64) {
            if (tid < nt) {
                int a = g_bucket[e * T_TOK + tbase + tid];
                ash[tid] = a;
                gsh[tid] = g_gates[a];
            } else { ash[tid] = -1; gsh[tid] = 0.f; }
        }
        __syncthreads();

        // stage x tile transposed
        {
            int a = ash[s_stage];
            const float4* xrow = (a >= 0)
                ? (const float4*)(x + (size_t)(a >> 1) * D_EMB) : (const float4*)0;
#pragma unroll 4
            for (int it = 0; it < 16; ++it) {
                int d4 = it * 4 + dq_stage;
                float4 v = make_float4(0.f, 0.f, 0.f, 0.f);
                if (a >= 0) v = xrow[d4];
                xs[(d4 * 4 + 0) * XS_STR + s_stage] = v.x;
                xs[(d4 * 4 + 1) * XS_STR + s_stage] = v.y;
                xs[(d4 * 4 + 2) * XS_STR + s_stage] = v.z;
                xs[(d4 * 4 + 3) * XS_STR + s_stage] = v.w;
            }
        }
        __syncthreads();

        // ---- fc1: 2tok x 8h per thread, packed f32x2, weights via LDG ----
        {
            u64 acc[2][4];
#pragma unroll
            for (int i = 0; i < 2; ++i)
#pragma unroll
                for (int j = 0; j < 4; ++j) acc[i][j] = 0ULL;

#pragma unroll 8
            for (int d = 0; d < D_EMB; ++d) {
                float2 xv = *(const float2*)(xs + d * XS_STR + tg * 2);
                u64 a0 = pack2(xv.x, xv.x);
                u64 a1 = pack2(xv.y, xv.y);
                ulonglong2 wA = *(const ulonglong2*)(w1e + (size_t)d * H_DIM);
                ulonglong2 wB = *(const ulonglong2*)(w1e + (size_t)d * H_DIM + 4);
                ffma2(acc[0][0], a0, wA.x); ffma2(acc[0][1], a0, wA.y);
                ffma2(acc[0][2], a0, wB.x); ffma2(acc[0][3], a0, wB.y);
                ffma2(acc[1][0], a1, wA.x); ffma2(acc[1][1], a1, wA.y);
                ffma2(acc[1][2], a1, wB.x); ffma2(acc[1][3], a1, wB.y);
            }
#pragma unroll
            for (int i = 0; i < 2; ++i)
#pragma unroll
                for (int j = 0; j < 4; ++j) {
                    float2 h = unpack2(acc[i][j]);
                    h.x = fmaxf(h.x + b1p[j].x, 0.f);
                    h.y = fmaxf(h.y + b1p[j].y, 0.f);
                    int hb = hg * 8 + j * 2;
                    hs[(hb)     * HS_STR + tg * 2 + i] = h.x;
                    hs[(hb + 1) * HS_STR + tg * 2 + i] = h.y;
                }
        }
        __syncthreads();

        // ---- fc2: part = gate * (h @ W2 + b2), weights via LDG ----
        int a0i = ash[tg * 2], a1i = ash[tg * 2 + 1];
        float g0 = gsh[tg * 2], g1 = gsh[tg * 2 + 1];
        u64 gp0 = pack2(g0, g0), gp1 = pack2(g1, g1);

#pragma unroll 1
        for (int oc = 0; oc < 4; ++oc) {
            int o = oc * 64 + hg * 8;
            const float* w2p = w2e + o;
            u64 acc[2][4];
#pragma unroll
            for (int i = 0; i < 2; ++i)
#pragma unroll
                for (int j = 0; j < 4; ++j) acc[i][j] = 0ULL;

#pragma unroll 8
            for (int k = 0; k < H_DIM; ++k) {
                float2 hv = *(const float2*)(hs + k * HS_STR + tg * 2);
                u64 a0 = pack2(hv.x, hv.x);
                u64 a1 = pack2(hv.y, hv.y);
                ulonglong2 wA = *(const ulonglong2*)(w2p + (size_t)k * D_EMB);
                ulonglong2 wB = *(const ulonglong2*)(w2p + (size_t)k * D_EMB + 4);
                ffma2(acc[0][0], a0, wA.x); ffma2(acc[0][1], a0, wA.y);
                ffma2(acc[0][2], a0, wB.x); ffma2(acc[0][3], a0, wB.y);
                ffma2(acc[1][0], a1, wA.x); ffma2(acc[1][1], a1, wA.y);
                ffma2(acc[1][2], a1, wB.x); ffma2(acc[1][3], a1, wB.y);
            }
            ulonglong2 bA = *(const ulonglong2*)(b2 + e * D_EMB + o);
            ulonglong2 bB = *(const ulonglong2*)(b2 + e * D_EMB + o + 4);
            if (a0i >= 0) {
                ulonglong2 r0, r1;
                r0.x = mul2(add2(acc[0][0], bA.x), gp0);
                r0.y = mul2(add2(acc[0][1], bA.y), gp0);
                r1.x = mul2(add2(acc[0][2], bB.x), gp0);
                r1.y = mul2(add2(acc[0][3], bB.y), gp0);
                float* dst = g_part + (size_t)a0i * D_EMB + o;
                *(ulonglong2*)dst       = r0;
                *(ulonglong2*)(dst + 4) = r1;
            }
            if (a1i >= 0) {
                ulonglong2 r0, r1;
                r0.x = mul2(add2(acc[1][0], bA.x), gp1);
                r0.y = mul2(add2(acc[1][1], bA.y), gp1);
                r1.x = mul2(add2(acc[1][2], bB.x), gp1);
                r1.y = mul2(add2(acc[1][3], bB.y), gp1);
                float* dst = g_part + (size_t)a1i * D_EMB + o;
                *(ulonglong2*)dst       = r0;
                *(ulonglong2*)(dst + 4) = r1;
            }
        }
    }
}

// ---------------- kernel C: combine -------------------------------------------
__global__ void __launch_bounds__(256) k_combine(float* __restrict__ out) {
    __shared__ float red[256];
    int tid = threadIdx.x;
    size_t f4 = (size_t)blockIdx.x * 256 + tid;
    size_t t  = f4 >> 6;
    int    q  = (int)(f4 & 63);

    float4 a = *((const float4*)(g_part + (t * 2)     * D_EMB) + q);
    float4 b = *((const float4*)(g_part + (t * 2 + 1) * D_EMB) + q);
    float4 y;
    y.x = a.x + b.x; y.y = a.y + b.y; y.z = a.z + b.z; y.w = a.w + b.w;

    float kd = fabsf(y.x) + fabsf(y.y) + fabsf(y.z) + fabsf(y.w);

    float4 o;
    o.x = y.x * 0.5f; o.y = y.y * 0.5f; o.z = y.z * 0.5f; o.w = y.w * 0.5f;
    ((float4*)out)[f4] = o;

    red[tid] = kd;
    __syncthreads();
    for (int s = 128; s; s >>= 1) {
        if (tid < s) red[tid] += red[tid + s];
        __syncthreads();
    }
    if (tid == 0) g_kd_part[blockIdx.x] = red[0];
}

// ---------------- kernel D: finalize loss + reset counters ---------------------
__global__ void __launch_bounds__(256) k_final(float* __restrict__ out, int out_size) {
    __shared__ float red[256];
    __shared__ float impS[N_EXP * 256];
    int tid = threadIdx.x;

    float s = 0.f;
    for (int i = tid; i < NBLK_C; i += 256) s += g_kd_part[i];
    red[tid] = s;
    __syncthreads();
    for (int st = 128; st; st >>= 1) {
        if (tid < st) red[tid] += red[tid + st];
        __syncthreads();
    }
    float kd_total = red[0];
    __syncthreads();

    float imp[N_EXP];
#pragma unroll
    for (int e = 0; e < N_EXP; ++e) imp[e] = 0.f;
    for (int a = tid; a < 2 * T_TOK; a += 256) {
        int e = g_eidx[a];
        float g = g_gates[a];
#pragma unroll
        for (int q = 0; q < N_EXP; ++q) if (q == e) imp[q] += g;
    }
#pragma unroll
    for (int e = 0; e < N_EXP; ++e) impS[e * 256 + tid] = imp[e];
    __syncthreads();
    for (int st = 128; st; st >>= 1) {
        if (tid < st)
#pragma unroll
            for (int e = 0; e < N_EXP; ++e)
                impS[e * 256 + tid] += impS[e * 256 + tid + st];
        __syncthreads();
    }

    if (tid == 0) {
        float iv[N_EXP], lv[N_EXP];
        float si = 0.f, sl = 0.f;
#pragma unroll
        for (int e = 0; e < N_EXP; ++e) {
            iv[e] = impS[e * 256];
            lv[e] = (float)g_count[e];
            si += iv[e]; sl += lv[e];
        }
        float mi = si / (float)N_EXP, ml = sl / (float)N_EXP;
        float vi = 0.f, vl = 0.f;
#pragma unroll
        for (int e = 0; e < N_EXP; ++e) {
            float di = iv[e] - mi; vi += di * di;
            float dl = lv[e] - ml; vl += dl * dl;
        }
        vi /= (float)(N_EXP - 1);
        vl /= (float)(N_EXP - 1);
        float aux = vi / (mi * mi + 1e-10f) + vl / (ml * ml + 1e-10f);
        float kd  = kd_total / (float)((size_t)T_TOK * D_EMB);
        if (out_size > T_TOK * D_EMB)
            out[(size_t)T_TOK * D_EMB] = aux + kd;
    }

    // reset expert counters for the next invocation (zero-init covers call #1)
    __syncthreads();
    if (tid < N_EXP) g_count[tid] = 0;
}

// ---------------- launch --------------------------------------------------------
extern "C" void kernel_launch(void* const* d_in, const int* in_sizes, int n_in,
                              void* d_out, int out_size) {
    const float* x  = (const float*)d_in[0];
    const float* wg = (const float*)d_in[1];
    const float* w1 = (const float*)d_in[2];
    const float* b1 = (const float*)d_in[3];
    const float* w2 = (const float*)d_in[4];
    const float* b2 = (const float*)d_in[5];
    float* out = (float*)d_out;

    const int SMEM_B = (D_EMB * XS_STR + H_DIM * HS_STR + 64) * (int)sizeof(float)
                       + 64 * (int)sizeof(int);

    cudaFuncSetAttribute(k_ffn, cudaFuncAttributeMaxDynamicSharedMemorySize, SMEM_B);

    k_gate<<<T_TOK / 32, 256>>>(x, wg);
    dim3 gB(T_TOK / CHUNK, N_EXP);
    k_ffn<<<gB, 256, SMEM_B>>>(x, w1, b1, w2, b2);
    k_combine<<<NBLK_C, 256>>>(out);
    k_final<<<1, 256>>>(out, out_size);
}

// round 7
// speedup vs baseline: 1.9021x; 1.9021x over previous
#include <cuda_runtime.h>
#include <math.h>

#define T_TOK   65536
#define D_EMB   256
#define H_DIM   64
#define N_EXP   10
#define CHUNK   128          // tokens per FFN block (2 passes of 64)
#define XS_STR  68
#define HS_STR  68
#define NBLK_C  16384
#define NBLK_G  (T_TOK / 32) // 2048 gating blocks

typedef unsigned long long u64;

__device__ __forceinline__ u64 pack2(float lo, float hi) {
    u64 r; asm("mov.b64 %0,{%1,%2};" : "=l"(r) : "f"(lo), "f"(hi)); return r;
}
__device__ __forceinline__ void ffma2(u64& d, u64 a, u64 b) {
    asm("fma.rn.f32x2 %0,%1,%2,%0;" : "+l"(d) : "l"(a), "l"(b));
}
__device__ __forceinline__ u64 add2(u64 a, u64 b) {
    u64 r; asm("add.rn.f32x2 %0,%1,%2;" : "=l"(r) : "l"(a), "l"(b)); return r;
}
__device__ __forceinline__ u64 mul2(u64 a, u64 b) {
    u64 r; asm("mul.rn.f32x2 %0,%1,%2;" : "=l"(r) : "l"(a), "l"(b)); return r;
}
__device__ __forceinline__ float2 unpack2(u64 v) {
    float2 r; asm("mov.b64 {%0,%1},%2;" : "=f"(r.x), "=f"(r.y) : "l"(v)); return r;
}

// ---------------- scratch (zero-initialized at module load) -------------------
__device__ int   g_count[N_EXP];          // zeroed by k_final tail each call
__device__ int   g_bucket[N_EXP * T_TOK];
__device__ float g_gates[T_TOK * 2];
__device__ float g_part [(size_t)T_TOK * 2 * D_EMB];
__device__ float g_kd_part[NBLK_C];
__device__ float g_imp_part[NBLK_G * N_EXP];   // per-gating-block importance partials

// ---------------- kernel A: gating + importance partials ----------------------
__global__ void __launch_bounds__(256) k_gate(const float* __restrict__ x,
                                              const float* __restrict__ wg) {
    __shared__ float wgs[N_EXP * D_EMB];          // transposed: [e][d], conflict-free
    __shared__ float impW[8][N_EXP];              // per-warp importance partials
    int tid = threadIdx.x;
    for (int i = tid; i < D_EMB * N_EXP; i += 256) {
        int e = i / D_EMB, d = i - e * D_EMB;
        wgs[i] = wg[d * N_EXP + e];
    }
    __syncthreads();

    int warp = tid >> 5, lane = tid & 31;
    int t0 = blockIdx.x * 32 + warp * 4;

    float impL[N_EXP];
#pragma unroll
    for (int e = 0; e < N_EXP; ++e) impL[e] = 0.f;

    for (int r = 0; r < 4; ++r) {
        int t = t0 + r;
        float part[N_EXP];
#pragma unroll
        for (int e = 0; e < N_EXP; ++e) part[e] = 0.f;
#pragma unroll
        for (int dd = 0; dd < 8; ++dd) {
            int d = dd * 32 + lane;
            float xv = x[(size_t)t * D_EMB + d];
#pragma unroll
            for (int e = 0; e < N_EXP; ++e)
                part[e] = fmaf(xv, wgs[e * D_EMB + d], part[e]);
        }
#pragma unroll
        for (int e = 0; e < N_EXP; ++e) {
#pragma unroll
            for (int off = 16; off; off >>= 1)
                part[e] += __shfl_xor_sync(0xffffffffu, part[e], off);
        }
        if (lane == 0) {
            float m0 = -1e30f; int e0 = 0;
#pragma unroll
            for (int e = 0; e < N_EXP; ++e) if (part[e] > m0) { m0 = part[e]; e0 = e; }
            float m1 = -1e30f; int e1 = 0;
#pragma unroll
            for (int e = 0; e < N_EXP; ++e) if (e != e0 && part[e] > m1) { m1 = part[e]; e1 = e; }
            float ex = expf(m1 - m0);
            float s  = 1.f + ex;
            float g0 = 1.f / s;
            float g1 = ex / s;
            g_gates[2 * t]     = g0;
            g_gates[2 * t + 1] = g1;
#pragma unroll
            for (int q = 0; q < N_EXP; ++q) {
                if (q == e0) impL[q] += g0;
                if (q == e1) impL[q] += g1;
            }
            int p0 = atomicAdd(&g_count[e0], 1);
            g_bucket[e0 * T_TOK + p0] = (t << 1);
            int p1 = atomicAdd(&g_count[e1], 1);
            g_bucket[e1 * T_TOK + p1] = (t << 1) | 1;
        }
    }

    if (lane == 0) {
#pragma unroll
        for (int e = 0; e < N_EXP; ++e) impW[warp][e] = impL[e];
    }
    __syncthreads();
    if (tid < N_EXP) {
        float s = 0.f;
#pragma unroll
        for (int w = 0; w < 8; ++w) s += impW[w][tid];   // fixed order: deterministic
        g_imp_part[blockIdx.x * N_EXP + tid] = s;
    }
}

// ---------------- kernel B: expert-grouped FFN --------------------------------
__global__ void __launch_bounds__(256, 2) k_ffn(const float* __restrict__ x,
                                                const float* __restrict__ w1,
                                                const float* __restrict__ b1,
                                                const float* __restrict__ w2,
                                                const float* __restrict__ b2) {
    int e = blockIdx.y;
    int n_total = g_count[e];
    int base = blockIdx.x * CHUNK;
    if (base >= n_total) return;

    extern __shared__ float sm[];
    float* xs  = sm;                              // [256][XS_STR] transposed x
    float* hs  = xs + D_EMB * XS_STR;             // [64][HS_STR]  transposed h
    float* gsh = hs + H_DIM * HS_STR;             // [64]
    int*   ash = (int*)(gsh + 64);                // [64]

    int tid = threadIdx.x;
    int tg = tid & 31;
    int hg = tid >> 5;

    const float* w1e = w1 + (size_t)e * D_EMB * H_DIM + hg * 8;
    const float* w2e = w2 + (size_t)e * H_DIM * D_EMB;

    float2 b1p[4];
#pragma unroll
    for (int j = 0; j < 4; ++j)
        b1p[j] = *(const float2*)(b1 + e * H_DIM + hg * 8 + j * 2);

    int s_stage  = tid & 63;
    int dq_stage = tid >> 6;

    for (int p = 0; p < CHUNK / 64; ++p) {
        int tbase = base + p * 64;
        if (tbase >= n_total) break;
        int nt = min(64, n_total - tbase);

        __syncthreads();
        if (tid < 64) {
            if (tid < nt) {
                int a = g_bucket[e * T_TOK + tbase + tid];
                ash[tid] = a;
                gsh[tid] = g_gates[a];
            } else { ash[tid] = -1; gsh[tid] = 0.f; }
        }
        __syncthreads();

        {
            int a = ash[s_stage];
            const float4* xrow = (a >= 0)
                ? (const float4*)(x + (size_t)(a >> 1) * D_EMB) : (const float4*)0;
#pragma unroll 4
            for (int it = 0; it < 16; ++it) {
                int d4 = it * 4 + dq_stage;
                float4 v = make_float4(0.f, 0.f, 0.f, 0.f);
                if (a >= 0) v = xrow[d4];
                xs[(d4 * 4 + 0) * XS_STR + s_stage] = v.x;
                xs[(d4 * 4 + 1) * XS_STR + s_stage] = v.y;
                xs[(d4 * 4 + 2) * XS_STR + s_stage] = v.z;
                xs[(d4 * 4 + 3) * XS_STR + s_stage] = v.w;
            }
        }
        __syncthreads();

        // ---- fc1 ----
        {
            u64 acc[2][4];
#pragma unroll
            for (int i = 0; i < 2; ++i)
#pragma unroll
                for (int j = 0; j < 4; ++j) acc[i][j] = 0ULL;

#pragma unroll 8
            for (int d = 0; d < D_EMB; ++d) {
                float2 xv = *(const float2*)(xs + d * XS_STR + tg * 2);
                u64 a0 = pack2(xv.x, xv.x);
                u64 a1 = pack2(xv.y, xv.y);
                ulonglong2 wA = *(const ulonglong2*)(w1e + (size_t)d * H_DIM);
                ulonglong2 wB = *(const ulonglong2*)(w1e + (size_t)d * H_DIM + 4);
                ffma2(acc[0][0], a0, wA.x); ffma2(acc[0][1], a0, wA.y);
                ffma2(acc[0][2], a0, wB.x); ffma2(acc[0][3], a0, wB.y);
                ffma2(acc[1][0], a1, wA.x); ffma2(acc[1][1], a1, wA.y);
                ffma2(acc[1][2], a1, wB.x); ffma2(acc[1][3], a1, wB.y);
            }
#pragma unroll
            for (int i = 0; i < 2; ++i)
#pragma unroll
                for (int j = 0; j < 4; ++j) {
                    float2 h = unpack2(acc[i][j]);
                    h.x = fmaxf(h.x + b1p[j].x, 0.f);
                    h.y = fmaxf(h.y + b1p[j].y, 0.f);
                    int hb = hg * 8 + j * 2;
                    hs[(hb)     * HS_STR + tg * 2 + i] = h.x;
                    hs[(hb + 1) * HS_STR + tg * 2 + i] = h.y;
                }
        }
        __syncthreads();

        // ---- fc2 ----
        int a0i = ash[tg * 2], a1i = ash[tg * 2 + 1];
        float g0 = gsh[tg * 2], g1 = gsh[tg * 2 + 1];
        u64 gp0 = pack2(g0, g0), gp1 = pack2(g1, g1);

#pragma unroll 1
        for (int oc = 0; oc < 4; ++oc) {
            int o = oc * 64 + hg * 8;
            const float* w2p = w2e + o;
            u64 acc[2][4];
#pragma unroll
            for (int i = 0; i < 2; ++i)
#pragma unroll
                for (int j = 0; j < 4; ++j) acc[i][j] = 0ULL;

#pragma unroll 8
            for (int k = 0; k < H_DIM; ++k) {
                float2 hv = *(const float2*)(hs + k * HS_STR + tg * 2);
                u64 a0 = pack2(hv.x, hv.x);
                u64 a1 = pack2(hv.y, hv.y);
                ulonglong2 wA = *(const ulonglong2*)(w2p + (size_t)k * D_EMB);
                ulonglong2 wB = *(const ulonglong2*)(w2p + (size_t)k * D_EMB + 4);
                ffma2(acc[0][0], a0, wA.x); ffma2(acc[0][1], a0, wA.y);
                ffma2(acc[0][2], a0, wB.x); ffma2(acc[0][3], a0, wB.y);
                ffma2(acc[1][0], a1, wA.x); ffma2(acc[1][1], a1, wA.y);
                ffma2(acc[1][2], a1, wB.x); ffma2(acc[1][3], a1, wB.y);
            }
            ulonglong2 bA = *(const ulonglong2*)(b2 + e * D_EMB + o);
            ulonglong2 bB = *(const ulonglong2*)(b2 + e * D_EMB + o + 4);
            if (a0i >= 0) {
                ulonglong2 r0, r1;
                r0.x = mul2(add2(acc[0][0], bA.x), gp0);
                r0.y = mul2(add2(acc[0][1], bA.y), gp0);
                r1.x = mul2(add2(acc[0][2], bB.x), gp0);
                r1.y = mul2(add2(acc[0][3], bB.y), gp0);
                float* dst = g_part + (size_t)a0i * D_EMB + o;
                *(ulonglong2*)dst       = r0;
                *(ulonglong2*)(dst + 4) = r1;
            }
            if (a1i >= 0) {
                ulonglong2 r0, r1;
                r0.x = mul2(add2(acc[1][0], bA.x), gp1);
                r0.y = mul2(add2(acc[1][1], bA.y), gp1);
                r1.x = mul2(add2(acc[1][2], bB.x), gp1);
                r1.y = mul2(add2(acc[1][3], bB.y), gp1);
                float* dst = g_part + (size_t)a1i * D_EMB + o;
                *(ulonglong2*)dst       = r0;
                *(ulonglong2*)(dst + 4) = r1;
            }
        }
    }
}

// ---------------- kernel C: combine -------------------------------------------
__global__ void __launch_bounds__(256) k_combine(float* __restrict__ out) {
    __shared__ float red[256];
    int tid = threadIdx.x;
    size_t f4 = (size_t)blockIdx.x * 256 + tid;
    size_t t  = f4 >> 6;
    int    q  = (int)(f4 & 63);

    float4 a = *((const float4*)(g_part + (t * 2)     * D_EMB) + q);
    float4 b = *((const float4*)(g_part + (t * 2 + 1) * D_EMB) + q);
    float4 y;
    y.x = a.x + b.x; y.y = a.y + b.y; y.z = a.z + b.z; y.w = a.w + b.w;

    float kd = fabsf(y.x) + fabsf(y.y) + fabsf(y.z) + fabsf(y.w);

    float4 o;
    o.x = y.x * 0.5f; o.y = y.y * 0.5f; o.z = y.z * 0.5f; o.w = y.w * 0.5f;
    ((float4*)out)[f4] = o;

    red[tid] = kd;
    __syncthreads();
    for (int s = 128; s; s >>= 1) {
        if (tid < s) red[tid] += red[tid + s];
        __syncthreads();
    }
    if (tid == 0) g_kd_part[blockIdx.x] = red[0];
}

// ---------------- kernel D: finalize loss + reset counters ---------------------
__global__ void __launch_bounds__(256) k_final(float* __restrict__ out, int out_size) {
    __shared__ float red[256];
    __shared__ float impS[N_EXP * 256];
    int tid = threadIdx.x;

    // kd total (deterministic tree over 16384 partials)
    float s = 0.f;
    for (int i = tid; i < NBLK_C; i += 256) s += g_kd_part[i];
    red[tid] = s;
    __syncthreads();
    for (int st = 128; st; st >>= 1) {
        if (tid < st) red[tid] += red[tid + st];
        __syncthreads();
    }
    float kd_total = red[0];
    __syncthreads();

    // importance: reduce 2048 per-block partials per expert (deterministic)
    float imp[N_EXP];
#pragma unroll
    for (int e = 0; e < N_EXP; ++e) imp[e] = 0.f;
    for (int i = tid; i < NBLK_G; i += 256) {
#pragma unroll
        for (int e = 0; e < N_EXP; ++e)
            imp[e] += g_imp_part[i * N_EXP + e];
    }
#pragma unroll
    for (int e = 0; e < N_EXP; ++e) impS[e * 256 + tid] = imp[e];
    __syncthreads();
    for (int st = 128; st; st >>= 1) {
        if (tid < st)
#pragma unroll
            for (int e = 0; e < N_EXP; ++e)
                impS[e * 256 + tid] += impS[e * 256 + tid + st];
        __syncthreads();
    }

    if (tid == 0) {
        float iv[N_EXP], lv[N_EXP];
        float si = 0.f, sl = 0.f;
#pragma unroll
        for (int e = 0; e < N_EXP; ++e) {
            iv[e] = impS[e * 256];
            lv[e] = (float)g_count[e];
            si += iv[e]; sl += lv[e];
        }
        float mi = si / (float)N_EXP, ml = sl / (float)N_EXP;
        float vi = 0.f, vl = 0.f;
#pragma unroll
        for (int e = 0; e < N_EXP; ++e) {
            float di = iv[e] - mi; vi += di * di;
            float dl = lv[e] - ml; vl += dl * dl;
        }
        vi /= (float)(N_EXP - 1);
        vl /= (float)(N_EXP - 1);
        float aux = vi / (mi * mi + 1e-10f) + vl / (ml * ml + 1e-10f);
        float kd  = kd_total / (float)((size_t)T_TOK * D_EMB);
        if (out_size > T_TOK * D_EMB)
            out[(size_t)T_TOK * D_EMB] = aux + kd;
    }

    // reset expert counters for the next invocation (zero-init covers call #1)
    __syncthreads();
    if (tid < N_EXP) g_count[tid] = 0;
}

// ---------------- launch --------------------------------------------------------
extern "C" void kernel_launch(void* const* d_in, const int* in_sizes, int n_in,
                              void* d_out, int out_size) {
    const float* x  = (const float*)d_in[0];
    const float* wg = (const float*)d_in[1];
    const float* w1 = (const float*)d_in[2];
    const float* b1 = (const float*)d_in[3];
    const float* w2 = (const float*)d_in[4];
    const float* b2 = (const float*)d_in[5];
    float* out = (float*)d_out;

    const int SMEM_B = (D_EMB * XS_STR + H_DIM * HS_STR + 64) * (int)sizeof(float)
                       + 64 * (int)sizeof(int);

    cudaFuncSetAttribute(k_ffn, cudaFuncAttributeMaxDynamicSharedMemorySize, SMEM_B);

    k_gate<<<NBLK_G, 256>>>(x, wg);
    dim3 gB(T_TOK / CHUNK, N_EXP);
    k_ffn<<<gB, 256, SMEM_B>>>(x, w1, b1, w2, b2);
    k_combine<<<NBLK_C, 256>>>(out);
    k_final<<<1, 256>>>(out, out_size);
}